// round 2
// baseline (speedup 1.0000x reference)
#include <cuda_runtime.h>

#define HDIM 2048
#define NBS 40        // B*S
#define BB 4
#define LL 4096
#define SS 10
#define NSPLIT 16
#define SCALE 0.022097086912079608f  // 1/sqrt(2048)

// scratch layout (float offsets)
#define OFF_KVEC 0
#define OFF_VVEC (NBS * HDIM)
#define OFF_VO   (2 * NBS * HDIM)
#define OFF_KK   (3 * NBS * HDIM)
#define OFF_PART (4 * NBS * HDIM)

__device__ float g_scratch[4 * NBS * HDIM + NSPLIT * NBS * HDIM];

// ---------------------------------------------------------------------------
// NT kernel: O[bs][o] = sum_h W[o][h] * Y[bs][h]
// MODE 0: W1=w_k, W2=w_v, Y=h_lojban -> writes kvec, vvec
// MODE 1: W1=w_o, Y=vvec (from scratch) -> writes vo
// warp-per-o; Y tiles staged in shared, reused by all 8 warps.
// ---------------------------------------------------------------------------
template <int MODE>
__global__ void __launch_bounds__(256) nt_kernel(const float* __restrict__ W1,
                                                 const float* __restrict__ W2,
                                                 const float* __restrict__ Yext)
{
    constexpr int NMAT = (MODE == 0) ? 2 : 1;
    __shared__ float sy[NBS][256];

    const float* Y = (MODE == 0) ? Yext : (g_scratch + OFF_VVEC);
    float* O1 = g_scratch + ((MODE == 0) ? OFF_KVEC : OFF_VO);
    float* O2 = g_scratch + OFF_VVEC;

    int warp = threadIdx.x >> 5;
    int lane = threadIdx.x & 31;
    int o = blockIdx.x * 8 + warp;

    float acc1[NBS];
    float acc2[NBS];
#pragma unroll
    for (int i = 0; i < NBS; i++) { acc1[i] = 0.f; acc2[i] = 0.f; }

    const float* w1row = W1 + (size_t)o * HDIM;
    const float* w2row = (NMAT == 2) ? (W2 + (size_t)o * HDIM) : W1;

    for (int kt = 0; kt < HDIM; kt += 256) {
        __syncthreads();
        for (int idx = threadIdx.x; idx < NBS * 64; idx += 256) {
            int r = idx >> 6, c = idx & 63;
            reinterpret_cast<float4*>(&sy[r][0])[c] =
                reinterpret_cast<const float4*>(Y + (size_t)r * HDIM + kt)[c];
        }
        __syncthreads();
#pragma unroll
        for (int j = 0; j < 2; j++) {
            int k = j * 128 + lane * 4;
            float4 w1 = *reinterpret_cast<const float4*>(w1row + kt + k);
            float4 w2 = make_float4(0.f, 0.f, 0.f, 0.f);
            if constexpr (NMAT == 2)
                w2 = *reinterpret_cast<const float4*>(w2row + kt + k);
#pragma unroll
            for (int bs = 0; bs < NBS; bs++) {
                float4 y4 = *reinterpret_cast<const float4*>(&sy[bs][k]);
                acc1[bs] += w1.x * y4.x + w1.y * y4.y + w1.z * y4.z + w1.w * y4.w;
                if constexpr (NMAT == 2)
                    acc2[bs] += w2.x * y4.x + w2.y * y4.y + w2.z * y4.z + w2.w * y4.w;
            }
        }
    }

#pragma unroll
    for (int bs = 0; bs < NBS; bs++) {
        float v = acc1[bs];
        v += __shfl_xor_sync(0xffffffffu, v, 16);
        v += __shfl_xor_sync(0xffffffffu, v, 8);
        v += __shfl_xor_sync(0xffffffffu, v, 4);
        v += __shfl_xor_sync(0xffffffffu, v, 2);
        v += __shfl_xor_sync(0xffffffffu, v, 1);
        if (lane == 0) O1[(size_t)bs * HDIM + o] = v;
        if constexpr (NMAT == 2) {
            float u = acc2[bs];
            u += __shfl_xor_sync(0xffffffffu, u, 16);
            u += __shfl_xor_sync(0xffffffffu, u, 8);
            u += __shfl_xor_sync(0xffffffffu, u, 4);
            u += __shfl_xor_sync(0xffffffffu, u, 2);
            u += __shfl_xor_sync(0xffffffffu, u, 1);
            if (lane == 0) O2[(size_t)bs * HDIM + o] = u;
        }
    }
}

// ---------------------------------------------------------------------------
// NN kernel: partial[sp][bs][i] = sum_{o in chunk sp} kvec[bs][o] * Wq[o][i]
// threads over i (coalesced Wq reads), kvec chunk broadcast from shared.
// ---------------------------------------------------------------------------
__global__ void __launch_bounds__(256) nn_kernel(const float* __restrict__ W)
{
    __shared__ float sa[NBS][128];
    const float* A = g_scratch + OFF_KVEC;
    float* P = g_scratch + OFF_PART + (size_t)blockIdx.y * (NBS * HDIM);
    int i = blockIdx.x * 256 + threadIdx.x;
    int o0 = blockIdx.y * 128;

    for (int idx = threadIdx.x; idx < NBS * 32; idx += 256) {
        int r = idx >> 5, c = idx & 31;
        reinterpret_cast<float4*>(&sa[r][0])[c] =
            reinterpret_cast<const float4*>(A + (size_t)r * HDIM + o0)[c];
    }
    __syncthreads();

    float acc[NBS];
#pragma unroll
    for (int bs = 0; bs < NBS; bs++) acc[bs] = 0.f;

    for (int o = 0; o < 128; o += 4) {
        float w0 = W[(size_t)(o0 + o + 0) * HDIM + i];
        float w1 = W[(size_t)(o0 + o + 1) * HDIM + i];
        float w2 = W[(size_t)(o0 + o + 2) * HDIM + i];
        float w3 = W[(size_t)(o0 + o + 3) * HDIM + i];
#pragma unroll
        for (int bs = 0; bs < NBS; bs++) {
            float4 a4 = *reinterpret_cast<const float4*>(&sa[bs][o]);
            acc[bs] += w0 * a4.x + w1 * a4.y + w2 * a4.z + w3 * a4.w;
        }
    }
#pragma unroll
    for (int bs = 0; bs < NBS; bs++)
        P[(size_t)bs * HDIM + i] = acc[bs];
}

// sum the NSPLIT partials, fold in 1/sqrt(H)
__global__ void __launch_bounds__(256) reduce_kernel()
{
    int idx = blockIdx.x * 256 + threadIdx.x;
    const float* P = g_scratch + OFF_PART;
    float s = 0.f;
#pragma unroll
    for (int sp = 0; sp < NSPLIT; sp++)
        s += P[(size_t)sp * (NBS * HDIM) + idx];
    g_scratch[OFF_KK + idx] = s * SCALE;
}

// ---------------------------------------------------------------------------
// Main fused kernel: per row l of x:
//   scores_s = x_l . kk[b][s]  (scale already folded into kk)
//   p = softmax(scores); out = x + alpha * sum_s p_s * vo[b][s]
// 512 threads, 4 rows per warp, kk/vo (160 KB) resident in shared.
// ---------------------------------------------------------------------------
__global__ void __launch_bounds__(512, 1) main_kernel(const float* __restrict__ X,
                                                      const float* __restrict__ alpha_p,
                                                      float* __restrict__ out)
{
    extern __shared__ float sm[];
    float* skk = sm;
    float* svo = sm + SS * HDIM;

    int b = blockIdx.y;
    const float* kkb = g_scratch + OFF_KK + (size_t)b * SS * HDIM;
    const float* vob = g_scratch + OFF_VO + (size_t)b * SS * HDIM;

    for (int idx = threadIdx.x; idx < SS * HDIM / 4; idx += 512) {
        reinterpret_cast<float4*>(skk)[idx] = reinterpret_cast<const float4*>(kkb)[idx];
        reinterpret_cast<float4*>(svo)[idx] = reinterpret_cast<const float4*>(vob)[idx];
    }
    float alpha = *alpha_p;
    __syncthreads();

    int warp = threadIdx.x >> 5;
    int lane = threadIdx.x & 31;
    int row0 = blockIdx.x * 64 + warp * 4;
    const float* xr = X + ((size_t)b * LL + row0) * HDIM;
    float* orow = out + ((size_t)b * LL + row0) * HDIM;

    float acc[4][10];
#pragma unroll
    for (int r = 0; r < 4; r++)
#pragma unroll
        for (int s = 0; s < 10; s++) acc[r][s] = 0.f;

    // Stage A: scores
    for (int c = 0; c < 16; c++) {
        int h = c * 128 + lane * 4;
        float4 x4[4];
#pragma unroll
        for (int r = 0; r < 4; r++)
            x4[r] = *reinterpret_cast<const float4*>(xr + (size_t)r * HDIM + h);
#pragma unroll
        for (int s = 0; s < 10; s++) {
            float4 k4 = *reinterpret_cast<const float4*>(skk + s * HDIM + h);
#pragma unroll
            for (int r = 0; r < 4; r++)
                acc[r][s] += x4[r].x * k4.x + x4[r].y * k4.y + x4[r].z * k4.z + x4[r].w * k4.w;
        }
    }

    // lane reduction (butterfly -> all lanes hold full sums)
#pragma unroll
    for (int r = 0; r < 4; r++)
#pragma unroll
        for (int s = 0; s < 10; s++) {
            float v = acc[r][s];
            v += __shfl_xor_sync(0xffffffffu, v, 16);
            v += __shfl_xor_sync(0xffffffffu, v, 8);
            v += __shfl_xor_sync(0xffffffffu, v, 4);
            v += __shfl_xor_sync(0xffffffffu, v, 2);
            v += __shfl_xor_sync(0xffffffffu, v, 1);
            acc[r][s] = v;
        }

    // softmax over S=10, fold alpha into probs
#pragma unroll
    for (int r = 0; r < 4; r++) {
        float m = acc[r][0];
#pragma unroll
        for (int s = 1; s < 10; s++) m = fmaxf(m, acc[r][s]);
        float sum = 0.f;
#pragma unroll
        for (int s = 0; s < 10; s++) {
            float e = __expf(acc[r][s] - m);
            acc[r][s] = e;
            sum += e;
        }
        float inv = alpha / sum;
#pragma unroll
        for (int s = 0; s < 10; s++) acc[r][s] *= inv;
    }

    // Stage B: out = x + sum_s p_s * vo_s
    for (int c = 0; c < 16; c++) {
        int h = c * 128 + lane * 4;
        float4 y4[4];
#pragma unroll
        for (int r = 0; r < 4; r++)
            y4[r] = *reinterpret_cast<const float4*>(xr + (size_t)r * HDIM + h);
#pragma unroll
        for (int s = 0; s < 10; s++) {
            float4 v4 = *reinterpret_cast<const float4*>(svo + s * HDIM + h);
#pragma unroll
            for (int r = 0; r < 4; r++) {
                y4[r].x += acc[r][s] * v4.x;
                y4[r].y += acc[r][s] * v4.y;
                y4[r].z += acc[r][s] * v4.z;
                y4[r].w += acc[r][s] * v4.w;
            }
        }
#pragma unroll
        for (int r = 0; r < 4; r++)
            *reinterpret_cast<float4*>(orow + (size_t)r * HDIM + h) = y4[r];
    }
}

extern "C" void kernel_launch(void* const* d_in, const int* in_sizes, int n_in,
                              void* d_out, int out_size)
{
    const float* x     = (const float*)d_in[0];  // h_english [4,4096,2048]
    const float* y     = (const float*)d_in[1];  // h_lojban  [4,10,2048]
    const float* wq    = (const float*)d_in[2];
    const float* wk    = (const float*)d_in[3];
    const float* wv    = (const float*)d_in[4];
    const float* wo    = (const float*)d_in[5];
    const float* alpha = (const float*)d_in[6];
    float* out = (float*)d_out;

    cudaFuncSetAttribute(main_kernel, cudaFuncAttributeMaxDynamicSharedMemorySize,
                         2 * SS * HDIM * (int)sizeof(float));

    // Stage 1: kvec = Y Wk^T, vvec = Y Wv^T
    nt_kernel<0><<<256, 256>>>(wk, wv, y);
    // Stage 2a: vo = vvec Wo^T
    nt_kernel<1><<<256, 256>>>(wo, nullptr, nullptr);
    // Stage 2b: kk = kvec Wq (split-o partials), then deterministic reduce (+scale)
    nn_kernel<<<dim3(8, NSPLIT), 256>>>(wq);
    reduce_kernel<<<(NBS * HDIM) / 256, 256>>>();
    // Fused attention-apply over all 16384 rows
    main_kernel<<<dim3(LL / 64, BB), 512, 2 * SS * HDIM * sizeof(float)>>>(x, alpha, out);
}

// round 4
// speedup vs baseline: 1.0042x; 1.0042x over previous
#include <cuda_runtime.h>

#define HDIM 2048
#define NBS 40        // B*S
#define BB 4
#define LL 4096
#define SS 10
#define NSPLIT 16
#define SCALE 0.022097086912079608f  // 1/sqrt(2048)

// scratch layout (float offsets)
#define OFF_KVEC 0
#define OFF_VVEC (NBS * HDIM)
#define OFF_VO   (2 * NBS * HDIM)
#define OFF_KK   (3 * NBS * HDIM)
#define OFF_PART (4 * NBS * HDIM)

__device__ __align__(16) float g_scratch[4 * NBS * HDIM + NSPLIT * NBS * HDIM];

typedef unsigned long long u64;

// ---- packed f32x2 helpers (Blackwell FFMA2; PTX-only) ----------------------
__device__ __forceinline__ u64 ffma2(u64 a, u64 b, u64 c) {
    u64 d;
    asm("fma.rn.f32x2 %0, %1, %2, %3;" : "=l"(d) : "l"(a), "l"(b), "l"(c));
    return d;
}
__device__ __forceinline__ u64 pack2(float lo, float hi) {
    u64 r;
    asm("mov.b64 %0, {%1, %2};" : "=l"(r) : "f"(lo), "f"(hi));
    return r;
}
__device__ __forceinline__ float hsum2(u64 v) {
    float lo, hi;
    asm("mov.b64 {%0, %1}, %2;" : "=f"(lo), "=f"(hi) : "l"(v));
    return lo + hi;
}
__device__ __forceinline__ float warp_sum(float v) {
    v += __shfl_xor_sync(0xffffffffu, v, 16);
    v += __shfl_xor_sync(0xffffffffu, v, 8);
    v += __shfl_xor_sync(0xffffffffu, v, 4);
    v += __shfl_xor_sync(0xffffffffu, v, 2);
    v += __shfl_xor_sync(0xffffffffu, v, 1);
    return v;
}

// ---------------------------------------------------------------------------
// Stage 1 NT kernel: kvec[bs][o] = sum_h w_k[o][h]*Y[bs][h], vvec likewise.
// warp-per-o; Y tiles staged in shared, reused by all 8 warps.
// ---------------------------------------------------------------------------
__global__ void __launch_bounds__(256) nt0_kernel(const float* __restrict__ Wk,
                                                  const float* __restrict__ Wv,
                                                  const float* __restrict__ Y)
{
    __shared__ __align__(16) float sy[NBS * 256];

    float* O1 = g_scratch + OFF_KVEC;
    float* O2 = g_scratch + OFF_VVEC;

    int warp = threadIdx.x >> 5;
    int lane = threadIdx.x & 31;
    int o = blockIdx.x * 8 + warp;

    u64 acc1[NBS], acc2[NBS];
#pragma unroll
    for (int i = 0; i < NBS; i++) { acc1[i] = 0ull; acc2[i] = 0ull; }

    const float* w1row = Wk + (size_t)o * HDIM;
    const float* w2row = Wv + (size_t)o * HDIM;

    for (int kt = 0; kt < HDIM; kt += 256) {
        __syncthreads();
        for (int idx = threadIdx.x; idx < NBS * 64; idx += 256) {
            int r = idx >> 6, c = idx & 63;
            reinterpret_cast<float4*>(&sy[r * 256])[c] =
                reinterpret_cast<const float4*>(Y + (size_t)r * HDIM + kt)[c];
        }
        __syncthreads();
#pragma unroll
        for (int j = 0; j < 2; j++) {
            int k = j * 128 + lane * 4;
            ulonglong2 w1 = *reinterpret_cast<const ulonglong2*>(w1row + kt + k);
            ulonglong2 w2 = *reinterpret_cast<const ulonglong2*>(w2row + kt + k);
#pragma unroll
            for (int bs = 0; bs < NBS; bs++) {
                ulonglong2 y2 = *reinterpret_cast<const ulonglong2*>(&sy[bs * 256 + k]);
                acc1[bs] = ffma2(w1.x, y2.x, acc1[bs]);
                acc1[bs] = ffma2(w1.y, y2.y, acc1[bs]);
                acc2[bs] = ffma2(w2.x, y2.x, acc2[bs]);
                acc2[bs] = ffma2(w2.y, y2.y, acc2[bs]);
            }
        }
    }

#pragma unroll
    for (int bs = 0; bs < NBS; bs++) {
        float v = warp_sum(hsum2(acc1[bs]));
        if (lane == 0) O1[(size_t)bs * HDIM + o] = v;
        float u = warp_sum(hsum2(acc2[bs]));
        if (lane == 0) O2[(size_t)bs * HDIM + o] = u;
    }
}

// ---------------------------------------------------------------------------
// Stage 2 fused kernel.
//   blocks [0,256):  vo[bs][o] = sum_h w_o[o][h]*vvec[bs][h]   (NT, warp-per-o)
//   blocks [256,384): partial[sp][bs][i] = sum_{o in sp chunk} kvec[bs][o]*Wq[o][i]
// ---------------------------------------------------------------------------
__global__ void __launch_bounds__(256) stage2_kernel(const float* __restrict__ Wo,
                                                     const float* __restrict__ Wq)
{
    __shared__ __align__(16) float sbuf[NBS * 256];

    if (blockIdx.x < 256) {
        // ---- NT path: vo = vvec @ Wo^T ----
        const float* Y = g_scratch + OFF_VVEC;
        float* O = g_scratch + OFF_VO;
        int warp = threadIdx.x >> 5;
        int lane = threadIdx.x & 31;
        int o = blockIdx.x * 8 + warp;

        u64 acc[NBS];
#pragma unroll
        for (int i = 0; i < NBS; i++) acc[i] = 0ull;
        const float* wrow = Wo + (size_t)o * HDIM;

        for (int kt = 0; kt < HDIM; kt += 256) {
            __syncthreads();
            for (int idx = threadIdx.x; idx < NBS * 64; idx += 256) {
                int r = idx >> 6, c = idx & 63;
                reinterpret_cast<float4*>(&sbuf[r * 256])[c] =
                    reinterpret_cast<const float4*>(Y + (size_t)r * HDIM + kt)[c];
            }
            __syncthreads();
#pragma unroll
            for (int j = 0; j < 2; j++) {
                int k = j * 128 + lane * 4;
                ulonglong2 w = *reinterpret_cast<const ulonglong2*>(wrow + kt + k);
#pragma unroll
                for (int bs = 0; bs < NBS; bs++) {
                    ulonglong2 y2 = *reinterpret_cast<const ulonglong2*>(&sbuf[bs * 256 + k]);
                    acc[bs] = ffma2(w.x, y2.x, acc[bs]);
                    acc[bs] = ffma2(w.y, y2.y, acc[bs]);
                }
            }
        }
#pragma unroll
        for (int bs = 0; bs < NBS; bs++) {
            float v = warp_sum(hsum2(acc[bs]));
            if (lane == 0) O[(size_t)bs * HDIM + o] = v;
        }
    } else {
        // ---- NN path: partial = kvec-chunk @ Wq ----
        int bid = blockIdx.x - 256;
        int sp = bid >> 3;          // 0..15
        int iblk = bid & 7;         // 0..7
        const float* A = g_scratch + OFF_KVEC;
        float* P = g_scratch + OFF_PART + (size_t)sp * (NBS * HDIM);
        int i = iblk * 256 + threadIdx.x;
        int o0 = sp * 128;

        float* sa = sbuf;  // [NBS][128]
        for (int idx = threadIdx.x; idx < NBS * 32; idx += 256) {
            int r = idx >> 5, c = idx & 31;
            reinterpret_cast<float4*>(&sa[r * 128])[c] =
                reinterpret_cast<const float4*>(A + (size_t)r * HDIM + o0)[c];
        }
        __syncthreads();

        u64 acc[NBS];
#pragma unroll
        for (int bs = 0; bs < NBS; bs++) acc[bs] = 0ull;

        for (int o = 0; o < 128; o += 4) {
            float w0 = Wq[(size_t)(o0 + o + 0) * HDIM + i];
            float w1 = Wq[(size_t)(o0 + o + 1) * HDIM + i];
            float w2 = Wq[(size_t)(o0 + o + 2) * HDIM + i];
            float w3 = Wq[(size_t)(o0 + o + 3) * HDIM + i];
            u64 wA = pack2(w0, w1);
            u64 wB = pack2(w2, w3);
#pragma unroll
            for (int bs = 0; bs < NBS; bs++) {
                ulonglong2 a2 = *reinterpret_cast<const ulonglong2*>(&sa[bs * 128 + o]);
                acc[bs] = ffma2(wA, a2.x, acc[bs]);
                acc[bs] = ffma2(wB, a2.y, acc[bs]);
            }
        }
#pragma unroll
        for (int bs = 0; bs < NBS; bs++)
            P[(size_t)bs * HDIM + i] = hsum2(acc[bs]);
    }
}

// sum the NSPLIT partials (float4-vectorized), fold in 1/sqrt(H)
__global__ void __launch_bounds__(256) reduce_kernel()
{
    int idx = blockIdx.x * 256 + threadIdx.x;   // float4 index
    const float4* P = reinterpret_cast<const float4*>(g_scratch + OFF_PART);
    float4 s = make_float4(0.f, 0.f, 0.f, 0.f);
#pragma unroll
    for (int sp = 0; sp < NSPLIT; sp++) {
        float4 p = P[(size_t)sp * (NBS * HDIM / 4) + idx];
        s.x += p.x; s.y += p.y; s.z += p.z; s.w += p.w;
    }
    s.x *= SCALE; s.y *= SCALE; s.z *= SCALE; s.w *= SCALE;
    reinterpret_cast<float4*>(g_scratch + OFF_KK)[idx] = s;
}

// ---------------------------------------------------------------------------
// Main fused kernel: per row l of x:
//   scores_s = x_l . kk[b][s]  (scale folded into kk)
//   p = softmax(scores); out = x + alpha * sum_s p_s * vo[b][s]
// 512 threads, 4 rows per warp, kk/vo (160 KB) resident in shared.
// ---------------------------------------------------------------------------
__global__ void __launch_bounds__(512, 1) main_kernel(const float* __restrict__ X,
                                                      const float* __restrict__ alpha_p,
                                                      float* __restrict__ out)
{
    extern __shared__ __align__(16) float sm[];
    float* skk = sm;
    float* svo = sm + SS * HDIM;

    int b = blockIdx.y;
    const float* kkb = g_scratch + OFF_KK + (size_t)b * SS * HDIM;
    const float* vob = g_scratch + OFF_VO + (size_t)b * SS * HDIM;

    for (int idx = threadIdx.x; idx < SS * HDIM / 4; idx += 512) {
        reinterpret_cast<float4*>(skk)[idx] = reinterpret_cast<const float4*>(kkb)[idx];
        reinterpret_cast<float4*>(svo)[idx] = reinterpret_cast<const float4*>(vob)[idx];
    }
    float alpha = *alpha_p;
    __syncthreads();

    int warp = threadIdx.x >> 5;
    int lane = threadIdx.x & 31;
    int row0 = blockIdx.x * 64 + warp * 4;
    const float* xr = X + ((size_t)b * LL + row0) * HDIM;
    float* orow = out + ((size_t)b * LL + row0) * HDIM;

    u64 acc[4][SS];
#pragma unroll
    for (int r = 0; r < 4; r++)
#pragma unroll
        for (int s = 0; s < SS; s++) acc[r][s] = 0ull;

    // Stage A: scores (packed f32x2 dot products)
#pragma unroll 2
    for (int c = 0; c < 16; c++) {
        int h = c * 128 + lane * 4;
        ulonglong2 x2[4];
#pragma unroll
        for (int r = 0; r < 4; r++)
            x2[r] = *reinterpret_cast<const ulonglong2*>(xr + (size_t)r * HDIM + h);
#pragma unroll
        for (int s = 0; s < SS; s++) {
            ulonglong2 k2 = *reinterpret_cast<const ulonglong2*>(skk + s * HDIM + h);
#pragma unroll
            for (int r = 0; r < 4; r++) {
                acc[r][s] = ffma2(x2[r].x, k2.x, acc[r][s]);
                acc[r][s] = ffma2(x2[r].y, k2.y, acc[r][s]);
            }
        }
    }

    // reduce + softmax (fold alpha into probs)
    float p[4][SS];
#pragma unroll
    for (int r = 0; r < 4; r++)
#pragma unroll
        for (int s = 0; s < SS; s++)
            p[r][s] = warp_sum(hsum2(acc[r][s]));

#pragma unroll
    for (int r = 0; r < 4; r++) {
        float m = p[r][0];
#pragma unroll
        for (int s = 1; s < SS; s++) m = fmaxf(m, p[r][s]);
        float sum = 0.f;
#pragma unroll
        for (int s = 0; s < SS; s++) {
            float e = __expf(p[r][s] - m);
            p[r][s] = e;
            sum += e;
        }
        float inv = alpha / sum;
#pragma unroll
        for (int s = 0; s < SS; s++) p[r][s] *= inv;
    }

    u64 pp[4][SS];
#pragma unroll
    for (int r = 0; r < 4; r++)
#pragma unroll
        for (int s = 0; s < SS; s++) pp[r][s] = pack2(p[r][s], p[r][s]);

    // Stage B: out = x + sum_s p_s * vo_s
#pragma unroll 2
    for (int c = 0; c < 16; c++) {
        int h = c * 128 + lane * 4;
        ulonglong2 y2[4];
#pragma unroll
        for (int r = 0; r < 4; r++)
            y2[r] = *reinterpret_cast<const ulonglong2*>(xr + (size_t)r * HDIM + h);
#pragma unroll
        for (int s = 0; s < SS; s++) {
            ulonglong2 v2 = *reinterpret_cast<const ulonglong2*>(svo + s * HDIM + h);
#pragma unroll
            for (int r = 0; r < 4; r++) {
                y2[r].x = ffma2(pp[r][s], v2.x, y2[r].x);
                y2[r].y = ffma2(pp[r][s], v2.y, y2[r].y);
            }
        }
#pragma unroll
        for (int r = 0; r < 4; r++)
            *reinterpret_cast<ulonglong2*>(orow + (size_t)r * HDIM + h) = y2[r];
    }
}

extern "C" void kernel_launch(void* const* d_in, const int* in_sizes, int n_in,
                              void* d_out, int out_size)
{
    const float* x     = (const float*)d_in[0];  // h_english [4,4096,2048]
    const float* y     = (const float*)d_in[1];  // h_lojban  [4,10,2048]
    const float* wq    = (const float*)d_in[2];
    const float* wk    = (const float*)d_in[3];
    const float* wv    = (const float*)d_in[4];
    const float* wo    = (const float*)d_in[5];
    const float* alpha = (const float*)d_in[6];
    float* out = (float*)d_out;

    (void)cudaFuncSetAttribute(main_kernel, cudaFuncAttributeMaxDynamicSharedMemorySize,
                               2 * SS * HDIM * (int)sizeof(float));

    // Stage 1: kvec = Y Wk^T, vvec = Y Wv^T
    nt0_kernel<<<256, 256>>>(wk, wv, y);
    // Stage 2 (fused): vo = vvec Wo^T  AND  kk partials = kvec Wq
    stage2_kernel<<<384, 256>>>(wo, wq);
    // Deterministic partial-sum reduce (+scale)
    reduce_kernel<<<(NBS * HDIM / 4) / 256, 256>>>();
    // Fused attention-apply over all 16384 rows
    main_kernel<<<dim3(LL / 64, BB), 512, 2 * SS * HDIM * sizeof(float)>>>(x, alpha, out);
}

// round 5
// speedup vs baseline: 1.0401x; 1.0357x over previous
#include <cuda_runtime.h>

#define HDIM 2048
#define NBS 40        // B*S
#define BB 4
#define LL 4096
#define SS 10
#define NSPLIT 16
#define SCALE 0.022097086912079608f  // 1/sqrt(2048)

// scratch layout (float offsets)
#define OFF_KVEC 0
#define OFF_VVEC (NBS * HDIM)
#define OFF_VO   (2 * NBS * HDIM)
#define OFF_KK   (3 * NBS * HDIM)
#define OFF_PART (4 * NBS * HDIM)

__device__ __align__(16) float g_scratch[4 * NBS * HDIM + NSPLIT * NBS * HDIM];

typedef unsigned long long u64;

// ---- packed f32x2 helpers (Blackwell FFMA2; PTX-only) ----------------------
__device__ __forceinline__ u64 ffma2(u64 a, u64 b, u64 c) {
    u64 d;
    asm("fma.rn.f32x2 %0, %1, %2, %3;" : "=l"(d) : "l"(a), "l"(b), "l"(c));
    return d;
}
__device__ __forceinline__ u64 pack2(float lo, float hi) {
    u64 r;
    asm("mov.b64 %0, {%1, %2};" : "=l"(r) : "f"(lo), "f"(hi));
    return r;
}
__device__ __forceinline__ float hsum2(u64 v) {
    float lo, hi;
    asm("mov.b64 {%0, %1}, %2;" : "=f"(lo), "=f"(hi) : "l"(v));
    return lo + hi;
}
__device__ __forceinline__ float warp_sum(float v) {
    v += __shfl_xor_sync(0xffffffffu, v, 16);
    v += __shfl_xor_sync(0xffffffffu, v, 8);
    v += __shfl_xor_sync(0xffffffffu, v, 4);
    v += __shfl_xor_sync(0xffffffffu, v, 2);
    v += __shfl_xor_sync(0xffffffffu, v, 1);
    return v;
}
__device__ __forceinline__ void stcs16(float* p, ulonglong2 v) {
    asm volatile("st.global.cs.v2.b64 [%0], {%1, %2};" :: "l"(p), "l"(v.x), "l"(v.y) : "memory");
}

// ---------------------------------------------------------------------------
// Stage 1 NT kernel: kvec[bs][o] = sum_h w_k[o][h]*Y[bs][h], vvec likewise.
// 2 outputs per warp, bs chunked by 10: each y LDS.128 feeds 16 ffma2.
// 128 blocks x 256 threads; 16 o per block.
// ---------------------------------------------------------------------------
__global__ void __launch_bounds__(256) nt0_kernel(const float* __restrict__ Wk,
                                                  const float* __restrict__ Wv,
                                                  const float* __restrict__ Y)
{
    __shared__ __align__(16) float sy[10 * 512];   // 20 KB

    float* O1 = g_scratch + OFF_KVEC;
    float* O2 = g_scratch + OFF_VVEC;

    int warp = threadIdx.x >> 5;
    int lane = threadIdx.x & 31;
    int o0 = blockIdx.x * 16 + warp * 2;

    const float* wk0 = Wk + (size_t)o0 * HDIM;
    const float* wk1 = wk0 + HDIM;
    const float* wv0 = Wv + (size_t)o0 * HDIM;
    const float* wv1 = wv0 + HDIM;

    for (int ch = 0; ch < 4; ch++) {
        const float* Ych = Y + (size_t)(ch * 10) * HDIM;

        u64 acc[10][4];
#pragma unroll
        for (int bs = 0; bs < 10; bs++)
#pragma unroll
            for (int m = 0; m < 4; m++) acc[bs][m] = 0ull;

        for (int kt = 0; kt < HDIM; kt += 512) {
            __syncthreads();
            for (int idx = threadIdx.x; idx < 10 * 128; idx += 256) {
                int r = idx >> 7, c = idx & 127;
                reinterpret_cast<float4*>(&sy[r * 512])[c] =
                    reinterpret_cast<const float4*>(Ych + (size_t)r * HDIM + kt)[c];
            }
            __syncthreads();
#pragma unroll
            for (int j = 0; j < 4; j++) {
                int kg = kt + j * 128 + lane * 4;
                int ks = j * 128 + lane * 4;
                ulonglong2 a0 = *reinterpret_cast<const ulonglong2*>(wk0 + kg);
                ulonglong2 a1 = *reinterpret_cast<const ulonglong2*>(wk1 + kg);
                ulonglong2 b0 = *reinterpret_cast<const ulonglong2*>(wv0 + kg);
                ulonglong2 b1 = *reinterpret_cast<const ulonglong2*>(wv1 + kg);
#pragma unroll
                for (int bs = 0; bs < 10; bs++) {
                    ulonglong2 y2 = *reinterpret_cast<const ulonglong2*>(&sy[bs * 512 + ks]);
                    acc[bs][0] = ffma2(a0.x, y2.x, acc[bs][0]);
                    acc[bs][0] = ffma2(a0.y, y2.y, acc[bs][0]);
                    acc[bs][1] = ffma2(a1.x, y2.x, acc[bs][1]);
                    acc[bs][1] = ffma2(a1.y, y2.y, acc[bs][1]);
                    acc[bs][2] = ffma2(b0.x, y2.x, acc[bs][2]);
                    acc[bs][2] = ffma2(b0.y, y2.y, acc[bs][2]);
                    acc[bs][3] = ffma2(b1.x, y2.x, acc[bs][3]);
                    acc[bs][3] = ffma2(b1.y, y2.y, acc[bs][3]);
                }
            }
        }

#pragma unroll
        for (int bs = 0; bs < 10; bs++) {
            int row = ch * 10 + bs;
            float v0 = warp_sum(hsum2(acc[bs][0]));
            float v1 = warp_sum(hsum2(acc[bs][1]));
            float v2 = warp_sum(hsum2(acc[bs][2]));
            float v3 = warp_sum(hsum2(acc[bs][3]));
            if (lane == 0) {
                O1[(size_t)row * HDIM + o0]     = v0;
                O1[(size_t)row * HDIM + o0 + 1] = v1;
                O2[(size_t)row * HDIM + o0]     = v2;
                O2[(size_t)row * HDIM + o0 + 1] = v3;
            }
        }
    }
}

// ---------------------------------------------------------------------------
// Stage 2 fused kernel.
//   blocks [0,128):  vo[bs][o] = sum_h w_o[o][h]*vvec[bs][h]   (NT, 2 o/warp)
//   blocks [128,256): partial[sp][bs][i] = sum_{o chunk} kvec[bs][o]*Wq[o][i]
// ---------------------------------------------------------------------------
__global__ void __launch_bounds__(256) stage2_kernel(const float* __restrict__ Wo,
                                                     const float* __restrict__ Wq)
{
    __shared__ __align__(16) float sbuf[20 * 512];  // 40 KB

    if (blockIdx.x < 128) {
        // ---- NT path: vo = vvec @ Wo^T, 2 outputs per warp, bs chunks of 20 ----
        const float* Y = g_scratch + OFF_VVEC;
        float* O = g_scratch + OFF_VO;
        int warp = threadIdx.x >> 5;
        int lane = threadIdx.x & 31;
        int o0 = blockIdx.x * 16 + warp * 2;

        const float* w0 = Wo + (size_t)o0 * HDIM;
        const float* w1 = w0 + HDIM;

        for (int ch = 0; ch < 2; ch++) {
            const float* Ych = Y + (size_t)(ch * 20) * HDIM;

            u64 acc[20][2];
#pragma unroll
            for (int bs = 0; bs < 20; bs++) { acc[bs][0] = 0ull; acc[bs][1] = 0ull; }

            for (int kt = 0; kt < HDIM; kt += 512) {
                __syncthreads();
                for (int idx = threadIdx.x; idx < 20 * 128; idx += 256) {
                    int r = idx >> 7, c = idx & 127;
                    reinterpret_cast<float4*>(&sbuf[r * 512])[c] =
                        reinterpret_cast<const float4*>(Ych + (size_t)r * HDIM + kt)[c];
                }
                __syncthreads();
#pragma unroll
                for (int j = 0; j < 4; j++) {
                    int kg = kt + j * 128 + lane * 4;
                    int ks = j * 128 + lane * 4;
                    ulonglong2 a0 = *reinterpret_cast<const ulonglong2*>(w0 + kg);
                    ulonglong2 a1 = *reinterpret_cast<const ulonglong2*>(w1 + kg);
#pragma unroll
                    for (int bs = 0; bs < 20; bs++) {
                        ulonglong2 y2 = *reinterpret_cast<const ulonglong2*>(&sbuf[bs * 512 + ks]);
                        acc[bs][0] = ffma2(a0.x, y2.x, acc[bs][0]);
                        acc[bs][0] = ffma2(a0.y, y2.y, acc[bs][0]);
                        acc[bs][1] = ffma2(a1.x, y2.x, acc[bs][1]);
                        acc[bs][1] = ffma2(a1.y, y2.y, acc[bs][1]);
                    }
                }
            }
#pragma unroll
            for (int bs = 0; bs < 20; bs++) {
                int row = ch * 20 + bs;
                float v0 = warp_sum(hsum2(acc[bs][0]));
                float v1 = warp_sum(hsum2(acc[bs][1]));
                if (lane == 0) {
                    O[(size_t)row * HDIM + o0]     = v0;
                    O[(size_t)row * HDIM + o0 + 1] = v1;
                }
            }
        }
    } else {
        // ---- NN path: partial = kvec-chunk @ Wq (broadcast LDS, cheap) ----
        int bid = blockIdx.x - 128;
        int sp = bid >> 3;          // 0..15
        int iblk = bid & 7;         // 0..7
        const float* A = g_scratch + OFF_KVEC;
        float* P = g_scratch + OFF_PART + (size_t)sp * (NBS * HDIM);
        int i = iblk * 256 + threadIdx.x;
        int o0 = sp * 128;

        float* sa = sbuf;  // [NBS][128]
        for (int idx = threadIdx.x; idx < NBS * 32; idx += 256) {
            int r = idx >> 5, c = idx & 31;
            reinterpret_cast<float4*>(&sa[r * 128])[c] =
                reinterpret_cast<const float4*>(A + (size_t)r * HDIM + o0)[c];
        }
        __syncthreads();

        u64 acc[NBS];
#pragma unroll
        for (int bs = 0; bs < NBS; bs++) acc[bs] = 0ull;

        for (int o = 0; o < 128; o += 4) {
            float w0 = Wq[(size_t)(o0 + o + 0) * HDIM + i];
            float w1 = Wq[(size_t)(o0 + o + 1) * HDIM + i];
            float w2 = Wq[(size_t)(o0 + o + 2) * HDIM + i];
            float w3 = Wq[(size_t)(o0 + o + 3) * HDIM + i];
            u64 wA = pack2(w0, w1);
            u64 wB = pack2(w2, w3);
#pragma unroll
            for (int bs = 0; bs < NBS; bs++) {
                ulonglong2 a2 = *reinterpret_cast<const ulonglong2*>(&sa[bs * 128 + o]);
                acc[bs] = ffma2(wA, a2.x, acc[bs]);
                acc[bs] = ffma2(wB, a2.y, acc[bs]);
            }
        }
#pragma unroll
        for (int bs = 0; bs < NBS; bs++)
            P[(size_t)bs * HDIM + i] = hsum2(acc[bs]);
    }
}

// sum the NSPLIT partials (float4-vectorized), fold in 1/sqrt(H)
__global__ void __launch_bounds__(256) reduce_kernel()
{
    int idx = blockIdx.x * 256 + threadIdx.x;   // float4 index
    const float4* P = reinterpret_cast<const float4*>(g_scratch + OFF_PART);
    float4 s = make_float4(0.f, 0.f, 0.f, 0.f);
#pragma unroll
    for (int sp = 0; sp < NSPLIT; sp++) {
        float4 p = P[(size_t)sp * (NBS * HDIM / 4) + idx];
        s.x += p.x; s.y += p.y; s.z += p.z; s.w += p.w;
    }
    s.x *= SCALE; s.y *= SCALE; s.z *= SCALE; s.w *= SCALE;
    reinterpret_cast<float4*>(g_scratch + OFF_KK)[idx] = s;
}

// ---------------------------------------------------------------------------
// Main fused kernel: per row l of x:
//   scores_s = x_l . kk[b][s]  (scale folded into kk)
//   p = softmax(scores); out = x + alpha * sum_s p_s * vo[b][s]
// 512 threads, 4 rows per warp, kk/vo (160 KB) resident in shared.
// 1 block/SM by design: keeps the stage-B X re-read inside L2.
// ---------------------------------------------------------------------------
__global__ void __launch_bounds__(512, 1) main_kernel(const float* __restrict__ X,
                                                      const float* __restrict__ alpha_p,
                                                      float* __restrict__ out)
{
    extern __shared__ __align__(16) float sm[];
    float* skk = sm;
    float* svo = sm + SS * HDIM;

    int b = blockIdx.y;
    const float* kkb = g_scratch + OFF_KK + (size_t)b * SS * HDIM;
    const float* vob = g_scratch + OFF_VO + (size_t)b * SS * HDIM;

    for (int idx = threadIdx.x; idx < SS * HDIM / 4; idx += 512) {
        reinterpret_cast<float4*>(skk)[idx] = reinterpret_cast<const float4*>(kkb)[idx];
        reinterpret_cast<float4*>(svo)[idx] = reinterpret_cast<const float4*>(vob)[idx];
    }
    float alpha = *alpha_p;
    __syncthreads();

    int warp = threadIdx.x >> 5;
    int lane = threadIdx.x & 31;
    int row0 = blockIdx.x * 64 + warp * 4;
    const float* xr = X + ((size_t)b * LL + row0) * HDIM;
    float* orow = out + ((size_t)b * LL + row0) * HDIM;

    u64 acc[4][SS];
#pragma unroll
    for (int r = 0; r < 4; r++)
#pragma unroll
        for (int s = 0; s < SS; s++) acc[r][s] = 0ull;

    // Stage A: scores (packed f32x2 dot products)
#pragma unroll 2
    for (int c = 0; c < 16; c++) {
        int h = c * 128 + lane * 4;
        ulonglong2 x2[4];
#pragma unroll
        for (int r = 0; r < 4; r++)
            x2[r] = *reinterpret_cast<const ulonglong2*>(xr + (size_t)r * HDIM + h);
#pragma unroll
        for (int s = 0; s < SS; s++) {
            ulonglong2 k2 = *reinterpret_cast<const ulonglong2*>(skk + s * HDIM + h);
#pragma unroll
            for (int r = 0; r < 4; r++) {
                acc[r][s] = ffma2(x2[r].x, k2.x, acc[r][s]);
                acc[r][s] = ffma2(x2[r].y, k2.y, acc[r][s]);
            }
        }
    }

    // reduce + softmax (fold alpha into probs)
    float p[4][SS];
#pragma unroll
    for (int r = 0; r < 4; r++)
#pragma unroll
        for (int s = 0; s < SS; s++)
            p[r][s] = warp_sum(hsum2(acc[r][s]));

#pragma unroll
    for (int r = 0; r < 4; r++) {
        float m = p[r][0];
#pragma unroll
        for (int s = 1; s < SS; s++) m = fmaxf(m, p[r][s]);
        float sum = 0.f;
#pragma unroll
        for (int s = 0; s < SS; s++) {
            float e = __expf(p[r][s] - m);
            p[r][s] = e;
            sum += e;
        }
        float inv = alpha / sum;
#pragma unroll
        for (int s = 0; s < SS; s++) p[r][s] *= inv;
    }

    u64 pp[4][SS];
#pragma unroll
    for (int r = 0; r < 4; r++)
#pragma unroll
        for (int s = 0; s < SS; s++) pp[r][s] = pack2(p[r][s], p[r][s]);

    // Stage B: out = x + sum_s p_s * vo_s  (streaming stores keep X in L2)
#pragma unroll 2
    for (int c = 0; c < 16; c++) {
        int h = c * 128 + lane * 4;
        ulonglong2 y2[4];
#pragma unroll
        for (int r = 0; r < 4; r++)
            y2[r] = *reinterpret_cast<const ulonglong2*>(xr + (size_t)r * HDIM + h);
#pragma unroll
        for (int s = 0; s < SS; s++) {
            ulonglong2 v2 = *reinterpret_cast<const ulonglong2*>(svo + s * HDIM + h);
#pragma unroll
            for (int r = 0; r < 4; r++) {
                y2[r].x = ffma2(pp[r][s], v2.x, y2[r].x);
                y2[r].y = ffma2(pp[r][s], v2.y, y2[r].y);
            }
        }
#pragma unroll
        for (int r = 0; r < 4; r++)
            stcs16(orow + (size_t)r * HDIM + h, y2[r]);
    }
}

extern "C" void kernel_launch(void* const* d_in, const int* in_sizes, int n_in,
                              void* d_out, int out_size)
{
    const float* x     = (const float*)d_in[0];  // h_english [4,4096,2048]
    const float* y     = (const float*)d_in[1];  // h_lojban  [4,10,2048]
    const float* wq    = (const float*)d_in[2];
    const float* wk    = (const float*)d_in[3];
    const float* wv    = (const float*)d_in[4];
    const float* wo    = (const float*)d_in[5];
    const float* alpha = (const float*)d_in[6];
    float* out = (float*)d_out;

    (void)cudaFuncSetAttribute(main_kernel, cudaFuncAttributeMaxDynamicSharedMemorySize,
                               2 * SS * HDIM * (int)sizeof(float));

    // Stage 1: kvec = Y Wk^T, vvec = Y Wv^T   (2 o per warp, 128 blocks)
    nt0_kernel<<<128, 256>>>(wk, wv, y);
    // Stage 2 (fused): vo = vvec Wo^T (2 o/warp) AND kk partials = kvec Wq
    stage2_kernel<<<256, 256>>>(wo, wq);
    // Deterministic partial-sum reduce (+scale)
    reduce_kernel<<<(NBS * HDIM / 4) / 256, 256>>>();
    // Fused attention-apply over all 16384 rows
    main_kernel<<<dim3(LL / 64, BB), 512, 2 * SS * HDIM * sizeof(float)>>>(x, alpha, out);
}

// round 6
// speedup vs baseline: 1.1974x; 1.1512x over previous
#include <cuda_runtime.h>

#define HDIM 2048
#define NBS 40        // B*S
#define BB 4
#define LL 4096
#define SS 10
#define NSPLIT 16
#define SCALE 0.022097086912079608f  // 1/sqrt(2048)

// scratch layout (float offsets)
#define OFF_KVEC 0
#define OFF_VVEC (NBS * HDIM)
#define OFF_VO   (2 * NBS * HDIM)
#define OFF_KK   (3 * NBS * HDIM)
#define OFF_PART (4 * NBS * HDIM)

__device__ __align__(16) float g_scratch[4 * NBS * HDIM + NSPLIT * NBS * HDIM];

typedef unsigned long long u64;

// ---- packed f32x2 helpers (Blackwell FFMA2; PTX-only) ----------------------
__device__ __forceinline__ u64 ffma2(u64 a, u64 b, u64 c) {
    u64 d;
    asm("fma.rn.f32x2 %0, %1, %2, %3;" : "=l"(d) : "l"(a), "l"(b), "l"(c));
    return d;
}
__device__ __forceinline__ u64 pack2(float lo, float hi) {
    u64 r;
    asm("mov.b64 %0, {%1, %2};" : "=l"(r) : "f"(lo), "f"(hi));
    return r;
}
__device__ __forceinline__ float hsum2(u64 v) {
    float lo, hi;
    asm("mov.b64 {%0, %1}, %2;" : "=f"(lo), "=f"(hi) : "l"(v));
    return lo + hi;
}
__device__ __forceinline__ float warp_sum(float v) {
    v += __shfl_xor_sync(0xffffffffu, v, 16);
    v += __shfl_xor_sync(0xffffffffu, v, 8);
    v += __shfl_xor_sync(0xffffffffu, v, 4);
    v += __shfl_xor_sync(0xffffffffu, v, 2);
    v += __shfl_xor_sync(0xffffffffu, v, 1);
    return v;
}
__device__ __forceinline__ void stcs16(float* p, ulonglong2 v) {
    asm volatile("st.global.cs.v2.b64 [%0], {%1, %2};" :: "l"(p), "l"(v.x), "l"(v.y) : "memory");
}

// ---------------------------------------------------------------------------
// NT core: one warp computes out[bs0..bs0+9][o0..o0+3] = sum_h W[o][h]*Y[bs][h]
// No shared memory, no barriers: Y rows (8 KB each, 40 total) are L1/L2-hot
// and each 16B Y load feeds 8 ffma2 (4 o). Deep MLP via unrolled k-loop.
// ---------------------------------------------------------------------------
__device__ __forceinline__ void nt_warp(const float* __restrict__ W,
                                        const float* __restrict__ Ybase,
                                        float* __restrict__ O,
                                        int o0, int bs0, int lane)
{
    const float* w0 = W + (size_t)o0 * HDIM;
    const float* w1 = w0 + HDIM;
    const float* w2 = w1 + HDIM;
    const float* w3 = w2 + HDIM;
    const float* Y0 = Ybase + (size_t)bs0 * HDIM;

    u64 acc[4][10];
#pragma unroll
    for (int i = 0; i < 4; i++)
#pragma unroll
        for (int bs = 0; bs < 10; bs++) acc[i][bs] = 0ull;

#pragma unroll 2
    for (int kt = 0; kt < 16; kt++) {
        int k = kt * 128 + lane * 4;
        ulonglong2 a0 = *reinterpret_cast<const ulonglong2*>(w0 + k);
        ulonglong2 a1 = *reinterpret_cast<const ulonglong2*>(w1 + k);
        ulonglong2 a2 = *reinterpret_cast<const ulonglong2*>(w2 + k);
        ulonglong2 a3 = *reinterpret_cast<const ulonglong2*>(w3 + k);
#pragma unroll
        for (int half = 0; half < 2; half++) {
            ulonglong2 y[5];
#pragma unroll
            for (int j = 0; j < 5; j++)
                y[j] = *reinterpret_cast<const ulonglong2*>(Y0 + (size_t)(half * 5 + j) * HDIM + k);
#pragma unroll
            for (int j = 0; j < 5; j++) {
                int bs = half * 5 + j;
                acc[0][bs] = ffma2(a0.x, y[j].x, acc[0][bs]);
                acc[0][bs] = ffma2(a0.y, y[j].y, acc[0][bs]);
                acc[1][bs] = ffma2(a1.x, y[j].x, acc[1][bs]);
                acc[1][bs] = ffma2(a1.y, y[j].y, acc[1][bs]);
                acc[2][bs] = ffma2(a2.x, y[j].x, acc[2][bs]);
                acc[2][bs] = ffma2(a2.y, y[j].y, acc[2][bs]);
                acc[3][bs] = ffma2(a3.x, y[j].x, acc[3][bs]);
                acc[3][bs] = ffma2(a3.y, y[j].y, acc[3][bs]);
            }
        }
    }

#pragma unroll
    for (int bs = 0; bs < 10; bs++)
#pragma unroll
        for (int i = 0; i < 4; i++) {
            float v = warp_sum(hsum2(acc[i][bs]));
            if (lane == 0) O[(size_t)(bs0 + bs) * HDIM + o0 + i] = v;
        }
}

// ---------------------------------------------------------------------------
// Stage 1: kvec = Y Wk^T, vvec = Y Wv^T.
// 512 blocks x 256 threads = 4096 warps; warp -> (matrix, bs-chunk, 4 o).
// ---------------------------------------------------------------------------
__global__ void __launch_bounds__(256, 2) nt0_kernel(const float* __restrict__ Wk,
                                                     const float* __restrict__ Wv,
                                                     const float* __restrict__ Y)
{
    int wg = blockIdx.x * 8 + (threadIdx.x >> 5);   // 0..4095
    int lane = threadIdx.x & 31;
    int mat = wg & 1;
    int chunk = (wg >> 1) & 3;
    int o0 = (wg >> 3) * 4;

    const float* W = mat ? Wv : Wk;
    float* O = g_scratch + (mat ? OFF_VVEC : OFF_KVEC);
    nt_warp(W, Y, O, o0, chunk * 10, lane);
}

// ---------------------------------------------------------------------------
// Stage 2: blocks [0,256): vo = vvec Wo^T (NT, warp = 4 o x 10 bs)
//          blocks [256,384): kk partials = kvec-chunk @ Wq (NN, broadcast smem)
// ---------------------------------------------------------------------------
__global__ void __launch_bounds__(256, 2) stage2_kernel(const float* __restrict__ Wo,
                                                        const float* __restrict__ Wq)
{
    if (blockIdx.x < 256) {
        int wg = blockIdx.x * 8 + (threadIdx.x >> 5);   // 0..2047
        int lane = threadIdx.x & 31;
        int chunk = wg & 3;
        int o0 = (wg >> 2) * 4;
        nt_warp(Wo, g_scratch + OFF_VVEC, g_scratch + OFF_VO, o0, chunk * 10, lane);
    } else {
        __shared__ __align__(16) float sa[NBS * 128];
        int bid = blockIdx.x - 256;
        int sp = bid >> 3;          // 0..15
        int iblk = bid & 7;         // 0..7
        const float* A = g_scratch + OFF_KVEC;
        float* P = g_scratch + OFF_PART + (size_t)sp * (NBS * HDIM);
        int i = iblk * 256 + threadIdx.x;
        int o0 = sp * 128;

        for (int idx = threadIdx.x; idx < NBS * 32; idx += 256) {
            int r = idx >> 5, c = idx & 31;
            reinterpret_cast<float4*>(&sa[r * 128])[c] =
                reinterpret_cast<const float4*>(A + (size_t)r * HDIM + o0)[c];
        }
        __syncthreads();

        u64 acc[NBS];
#pragma unroll
        for (int bs = 0; bs < NBS; bs++) acc[bs] = 0ull;

#pragma unroll 4
        for (int o = 0; o < 128; o += 4) {
            float w0 = Wq[(size_t)(o0 + o + 0) * HDIM + i];
            float w1 = Wq[(size_t)(o0 + o + 1) * HDIM + i];
            float w2 = Wq[(size_t)(o0 + o + 2) * HDIM + i];
            float w3 = Wq[(size_t)(o0 + o + 3) * HDIM + i];
            u64 wA = pack2(w0, w1);
            u64 wB = pack2(w2, w3);
#pragma unroll
            for (int bs = 0; bs < NBS; bs++) {
                ulonglong2 a2 = *reinterpret_cast<const ulonglong2*>(&sa[bs * 128 + o]);
                acc[bs] = ffma2(wA, a2.x, acc[bs]);
                acc[bs] = ffma2(wB, a2.y, acc[bs]);
            }
        }
#pragma unroll
        for (int bs = 0; bs < NBS; bs++)
            P[(size_t)bs * HDIM + i] = hsum2(acc[bs]);
    }
}

// sum the NSPLIT partials (float4-vectorized), fold in 1/sqrt(H)
__global__ void __launch_bounds__(256) reduce_kernel()
{
    int idx = blockIdx.x * 256 + threadIdx.x;   // float4 index
    const float4* P = reinterpret_cast<const float4*>(g_scratch + OFF_PART);
    float4 s = make_float4(0.f, 0.f, 0.f, 0.f);
#pragma unroll
    for (int sp = 0; sp < NSPLIT; sp++) {
        float4 p = P[(size_t)sp * (NBS * HDIM / 4) + idx];
        s.x += p.x; s.y += p.y; s.z += p.z; s.w += p.w;
    }
    s.x *= SCALE; s.y *= SCALE; s.z *= SCALE; s.w *= SCALE;
    reinterpret_cast<float4*>(g_scratch + OFF_KK)[idx] = s;
}

// ---------------------------------------------------------------------------
// Main fused kernel: per row l of x:
//   scores_s = x_l . kk[b][s]  (scale folded into kk)
//   p = softmax(scores); out = x + alpha * sum_s p_s * vo[b][s]
// 1024 threads, 2 rows per warp (64 rows/block), kk/vo (160 KB) in shared.
// 32 resident warps/SM (vs 16 before) for latency tolerance.
// ---------------------------------------------------------------------------
__global__ void __launch_bounds__(1024, 1) main_kernel(const float* __restrict__ X,
                                                       const float* __restrict__ alpha_p,
                                                       float* __restrict__ out)
{
    extern __shared__ __align__(16) float sm[];
    float* skk = sm;
    float* svo = sm + SS * HDIM;

    int b = blockIdx.y;
    const float* kkb = g_scratch + OFF_KK + (size_t)b * SS * HDIM;
    const float* vob = g_scratch + OFF_VO + (size_t)b * SS * HDIM;

    for (int idx = threadIdx.x; idx < SS * HDIM / 4; idx += 1024) {
        reinterpret_cast<float4*>(skk)[idx] = reinterpret_cast<const float4*>(kkb)[idx];
        reinterpret_cast<float4*>(svo)[idx] = reinterpret_cast<const float4*>(vob)[idx];
    }
    float alpha = *alpha_p;
    __syncthreads();

    int warp = threadIdx.x >> 5;
    int lane = threadIdx.x & 31;
    int row0 = blockIdx.x * 64 + warp * 2;
    const float* xr = X + ((size_t)b * LL + row0) * HDIM;
    float* orow = out + ((size_t)b * LL + row0) * HDIM;

    u64 acc[2][SS];
#pragma unroll
    for (int r = 0; r < 2; r++)
#pragma unroll
        for (int s = 0; s < SS; s++) acc[r][s] = 0ull;

    // Stage A: scores (packed f32x2 dot products)
    for (int c = 0; c < 16; c++) {
        int h = c * 128 + lane * 4;
        ulonglong2 x2[2];
#pragma unroll
        for (int r = 0; r < 2; r++)
            x2[r] = *reinterpret_cast<const ulonglong2*>(xr + (size_t)r * HDIM + h);
#pragma unroll
        for (int s = 0; s < SS; s++) {
            ulonglong2 k2 = *reinterpret_cast<const ulonglong2*>(skk + s * HDIM + h);
#pragma unroll
            for (int r = 0; r < 2; r++) {
                acc[r][s] = ffma2(x2[r].x, k2.x, acc[r][s]);
                acc[r][s] = ffma2(x2[r].y, k2.y, acc[r][s]);
            }
        }
    }

    // reduce + softmax (fold alpha into probs)
    float p[2][SS];
#pragma unroll
    for (int r = 0; r < 2; r++)
#pragma unroll
        for (int s = 0; s < SS; s++)
            p[r][s] = warp_sum(hsum2(acc[r][s]));

#pragma unroll
    for (int r = 0; r < 2; r++) {
        float m = p[r][0];
#pragma unroll
        for (int s = 1; s < SS; s++) m = fmaxf(m, p[r][s]);
        float sum = 0.f;
#pragma unroll
        for (int s = 0; s < SS; s++) {
            float e = __expf(p[r][s] - m);
            p[r][s] = e;
            sum += e;
        }
        float inv = alpha / sum;
#pragma unroll
        for (int s = 0; s < SS; s++) p[r][s] *= inv;
    }

    u64 pp[2][SS];
#pragma unroll
    for (int r = 0; r < 2; r++)
#pragma unroll
        for (int s = 0; s < SS; s++) pp[r][s] = pack2(p[r][s], p[r][s]);

    // Stage B: out = x + sum_s p_s * vo_s  (streaming stores keep X in L2)
    for (int c = 0; c < 16; c++) {
        int h = c * 128 + lane * 4;
        ulonglong2 y2[2];
#pragma unroll
        for (int r = 0; r < 2; r++)
            y2[r] = *reinterpret_cast<const ulonglong2*>(xr + (size_t)r * HDIM + h);
#pragma unroll
        for (int s = 0; s < SS; s++) {
            ulonglong2 v2 = *reinterpret_cast<const ulonglong2*>(svo + s * HDIM + h);
#pragma unroll
            for (int r = 0; r < 2; r++) {
                y2[r].x = ffma2(pp[r][s], v2.x, y2[r].x);
                y2[r].y = ffma2(pp[r][s], v2.y, y2[r].y);
            }
        }
#pragma unroll
        for (int r = 0; r < 2; r++)
            stcs16(orow + (size_t)r * HDIM + h, y2[r]);
    }
}

extern "C" void kernel_launch(void* const* d_in, const int* in_sizes, int n_in,
                              void* d_out, int out_size)
{
    const float* x     = (const float*)d_in[0];  // h_english [4,4096,2048]
    const float* y     = (const float*)d_in[1];  // h_lojban  [4,10,2048]
    const float* wq    = (const float*)d_in[2];
    const float* wk    = (const float*)d_in[3];
    const float* wv    = (const float*)d_in[4];
    const float* wo    = (const float*)d_in[5];
    const float* alpha = (const float*)d_in[6];
    float* out = (float*)d_out;

    (void)cudaFuncSetAttribute(main_kernel, cudaFuncAttributeMaxDynamicSharedMemorySize,
                               2 * SS * HDIM * (int)sizeof(float));

    // Stage 1: kvec = Y Wk^T, vvec = Y Wv^T  (barrier-free, 4096 warps)
    nt0_kernel<<<512, 256>>>(wk, wv, y);
    // Stage 2 (fused): vo = vvec Wo^T  AND  kk partials = kvec Wq
    stage2_kernel<<<384, 256>>>(wo, wq);
    // Deterministic partial-sum reduce (+scale)
    reduce_kernel<<<(NBS * HDIM / 4) / 256, 256>>>();
    // Fused attention-apply over all 16384 rows (2 rows/warp, 32 warps/SM)
    main_kernel<<<dim3(LL / 64, BB), 1024, 2 * SS * HDIM * sizeof(float)>>>(x, alpha, out);
}